// round 6
// baseline (speedup 1.0000x reference)
#include <cuda_runtime.h>
#include <cmath>

#define B_   256
#define DIN_ 1024
#define DG_  1024
#define U_   512
#define D_   16
#define M_   256
#define G_   8

#define NB 8      // b per fused block
#define NU 8      // u per fused block
#define SP 264    // S pitch (floats)

#define KSPLIT1 4
#define KSPLIT2 2

__device__ float g_h[B_ * DG_];               // 1 MB: h
__device__ float g_hp[KSPLIT1][B_ * DG_];     // 4 MB: GEMM1 split-K partials
__device__ float g_ap[KSPLIT2][B_ * U_ * D_]; // 16 MB: GEMM2 split-K partials

// ---------------------------------------------------------------------------
// f32x2 helpers
// ---------------------------------------------------------------------------
typedef unsigned long long ull;
union F4U { float4 f; ull p[2]; float s[4]; };

__device__ __forceinline__ ull pk2(float a, float b) {
    ull r; asm("mov.b64 %0, {%1, %2};" : "=l"(r) : "f"(a), "f"(b)); return r;
}
__device__ __forceinline__ void upk2(ull v, float& a, float& b) {
    asm("mov.b64 {%0, %1}, %2;" : "=f"(a), "=f"(b) : "l"(v));
}
__device__ __forceinline__ void ffma2(ull& d, ull a, ull b) {
    asm("fma.rn.f32x2 %0, %1, %2, %0;" : "+l"(d) : "l"(a), "l"(b));
}
__device__ __forceinline__ ull add2(ull a, ull b) {
    ull r; asm("add.rn.f32x2 %0, %1, %2;" : "=l"(r) : "l"(a), "l"(b)); return r;
}

// ---------------------------------------------------------------------------
// fp32 SGEMM core, packed-pair inner product, optional bias, k-range slice.
// ---------------------------------------------------------------------------
template<int BM, int BN, int BK, int TM, int TN, int THREADS, bool BIAS>
__global__ void __launch_bounds__(THREADS) sgemm_core(
        const float* __restrict__ A, const float* __restrict__ Bm,
        const float* __restrict__ bias, float* __restrict__ C,
        int N, int K, int kChunk, int sliceStride)
{
    static_assert((BN / TN) * (BM / TM) == THREADS, "thread tiling mismatch");
    __shared__ float As[BK][BM + 4];
    __shared__ float Bs[BK][BN];

    const int tid = threadIdx.x;
    const int bx = blockIdx.x, by = blockIdx.y;
    const int kBegin = blockIdx.z * kChunk;
    const int kEnd   = kBegin + kChunk;
    float* Cs = C + (size_t)blockIdx.z * sliceStride;

    constexpr int TX = BN / TN;
    const int tx = tid % TX;
    const int ty = tid / TX;

    constexpr int LA = (BM * BK / 4) / THREADS;
    constexpr int LB = (BK * BN / 4) / THREADS;
    static_assert(LA >= 1 && LB >= 1, "tile too small");

    ull acc2[TM / 2][TN];
#pragma unroll
    for (int r = 0; r < TM / 2; r++)
#pragma unroll
        for (int c = 0; c < TN; c++) acc2[r][c] = 0ull;

    const float* Ablk = A + (size_t)by * BM * K;
    const float* Bblk = Bm + (size_t)bx * BN;

#pragma unroll
    for (int i = 0; i < LA; i++) {
        int a = tid + i * THREADS;
        int row = a / (BK / 4), kq = a % (BK / 4);
        float4 v = *(const float4*)(Ablk + (size_t)row * K + kBegin + kq * 4);
        As[kq*4+0][row] = v.x; As[kq*4+1][row] = v.y;
        As[kq*4+2][row] = v.z; As[kq*4+3][row] = v.w;
    }
#pragma unroll
    for (int i = 0; i < LB; i++) {
        int b = tid + i * THREADS;
        int kr = b / (BN / 4), nq = b % (BN / 4);
        *(float4*)(&Bs[kr][nq*4]) =
            *(const float4*)(Bblk + (size_t)(kBegin + kr) * N + nq * 4);
    }
    __syncthreads();

    for (int k0 = kBegin; k0 < kEnd; k0 += BK) {
        float4 nA[LA], nB[LB];
        const bool more = (k0 + BK) < kEnd;
        if (more) {
#pragma unroll
            for (int i = 0; i < LA; i++) {
                int a = tid + i * THREADS;
                int row = a / (BK / 4), kq = a % (BK / 4);
                nA[i] = *(const float4*)(Ablk + (size_t)row * K + k0 + BK + kq * 4);
            }
#pragma unroll
            for (int i = 0; i < LB; i++) {
                int b = tid + i * THREADS;
                int kr = b / (BN / 4), nq = b % (BN / 4);
                nB[i] = *(const float4*)(Bblk + (size_t)(k0 + BK + kr) * N + nq * 4);
            }
        }

#pragma unroll
        for (int k = 0; k < BK; k++) {
            ull ap[TM / 2];
#pragma unroll
            for (int q = 0; q < TM / 4; q++) {
                F4U t; t.f = *(const float4*)(&As[k][ty*TM + q*4]);
                ap[2*q]   = t.p[0];
                ap[2*q+1] = t.p[1];
            }
            ull bd[TN];
#pragma unroll
            for (int q = 0; q < TN / 4; q++) {
                float4 v = *(const float4*)(&Bs[k][tx*TN + q*4]);
                bd[q*4+0] = pk2(v.x, v.x); bd[q*4+1] = pk2(v.y, v.y);
                bd[q*4+2] = pk2(v.z, v.z); bd[q*4+3] = pk2(v.w, v.w);
            }
#pragma unroll
            for (int r = 0; r < TM / 2; r++)
#pragma unroll
                for (int c = 0; c < TN; c++)
                    ffma2(acc2[r][c], ap[r], bd[c]);
        }

        if (more) {
            __syncthreads();
#pragma unroll
            for (int i = 0; i < LA; i++) {
                int a = tid + i * THREADS;
                int row = a / (BK / 4), kq = a % (BK / 4);
                As[kq*4+0][row] = nA[i].x; As[kq*4+1][row] = nA[i].y;
                As[kq*4+2][row] = nA[i].z; As[kq*4+3][row] = nA[i].w;
            }
#pragma unroll
            for (int i = 0; i < LB; i++) {
                int b = tid + i * THREADS;
                int kr = b / (BN / 4), nq = b % (BN / 4);
                *(float4*)(&Bs[kr][nq*4]) = nB[i];
            }
            __syncthreads();
        }
    }

#pragma unroll
    for (int r2 = 0; r2 < TM / 2; r2++) {
        float s[2][TN];
#pragma unroll
        for (int c = 0; c < TN; c++) upk2(acc2[r2][c], s[0][c], s[1][c]);
#pragma unroll
        for (int h = 0; h < 2; h++) {
            int row = by*BM + ty*TM + 2*r2 + h;
#pragma unroll
            for (int c = 0; c < TN; c += 4) {
                int col = bx*BN + tx*TN + c;
                float4 v;
                if (BIAS) {
                    v.x = s[h][c+0] + bias[col+0];
                    v.y = s[h][c+1] + bias[col+1];
                    v.z = s[h][c+2] + bias[col+2];
                    v.w = s[h][c+3] + bias[col+3];
                } else {
                    v.x = s[h][c+0]; v.y = s[h][c+1];
                    v.z = s[h][c+2]; v.w = s[h][c+3];
                }
                *(float4*)(Cs + (size_t)row * N + col) = v;
            }
        }
    }
}

// ---------------------------------------------------------------------------
// reduce GEMM1 split-K partials + bias -> g_h
// ---------------------------------------------------------------------------
__global__ void __launch_bounds__(256) reduce_h(const float* __restrict__ bias)
{
    int i = blockIdx.x * 256 + threadIdx.x;
    int col4 = i & (DG_/4 - 1);
    float4 a = *(const float4*)(&g_hp[0][i*4]);
    float4 b = *(const float4*)(&g_hp[1][i*4]);
    float4 c = *(const float4*)(&g_hp[2][i*4]);
    float4 d = *(const float4*)(&g_hp[3][i*4]);
    float4 bb = *(const float4*)(bias + col4*4);
    float4 o;
    o.x = a.x + b.x + c.x + d.x + bb.x;
    o.y = a.y + b.y + c.y + d.y + bb.y;
    o.z = a.z + b.z + c.z + d.z + bb.z;
    o.w = a.w + b.w + c.w + d.w + bb.w;
    *(float4*)(&g_h[i*4]) = o;
}

// ---------------------------------------------------------------------------
// reduce GEMM2 split-K partials + bias -> attention (d_out)
// ---------------------------------------------------------------------------
__global__ void __launch_bounds__(256) reduce_att(const float* __restrict__ bias,
                                                  float* __restrict__ attn)
{
    int i = blockIdx.x * 256 + threadIdx.x;        // float4 index over B*U*D/4
    int col4 = i & (U_*D_/4 - 1);
    float4 a = *(const float4*)(&g_ap[0][i*4]);
    float4 b = *(const float4*)(&g_ap[1][i*4]);
    float4 bb = *(const float4*)(bias + col4*4);
    float4 o;
    o.x = a.x + b.x + bb.x;
    o.y = a.y + b.y + bb.y;
    o.z = a.z + b.z + bb.z;
    o.w = a.w + b.w + bb.w;
    *(float4*)(attn + (size_t)i*4) = o;
}

// ---------------------------------------------------------------------------
// Fused v3: block = (8 b, 8 u), full m=256 resident, 2 CTAs/SM.
// ---------------------------------------------------------------------------
#define SA_UP 132   // per-u sA block pitch (floats): 16d*8b + 4 pad
#define SM_FLOATS (NB*NU*SP + NU*SA_UP + NU*64*16)

__global__ void __launch_bounds__(256, 2) fused_attn(
        const float* __restrict__ attn,   // [B,U,D]
        const float* __restrict__ Ma,     // [M,U,D]
        const float* __restrict__ Mv,     // [M,U,D]
        const float* __restrict__ temp,   // [U]
        float* __restrict__ wout,         // [B,M,U]
        float* __restrict__ outp)         // [B,U,D]
{
    extern __shared__ float sm[];
    float*  sS   = sm;                        // 64 rows x 264  (row = b*NU + u)
    float*  sA   = sS + NB*NU*SP;             // [u]: pitch 132, inside [d][b(8)]
    float4* sMv4 = (float4*)(sA + NU*SA_UP);  // [u][64m x 4] swizzled chunk

    const int b0  = blockIdx.x * NB;
    const int u0  = blockIdx.y * NU;
    const int tid = threadIdx.x;
    const int lane = tid & 31;
    const int wu   = tid >> 5;        // warp <-> u
    const int u    = u0 + wu;

    // ---- stage attn tile -> sA[u][d][b]  (1024 floats) ----
    {
        int bi = tid >> 5;            // 0..7
        int uu = (tid >> 2) & 7;
        int dq = tid & 3;
        float4 v = *(const float4*)(attn + ((size_t)(b0+bi)*U_ + u0+uu)*D_ + dq*4);
        sA[uu*SA_UP + (dq*4+0)*8 + bi] = v.x;
        sA[uu*SA_UP + (dq*4+1)*8 + bi] = v.y;
        sA[uu*SA_UP + (dq*4+2)*8 + bi] = v.z;
        sA[uu*SA_UP + (dq*4+3)*8 + bi] = v.w;
    }
    const float tu = temp[u];
    __syncthreads();

    // ---- stage 1: scores S[8b,256m] per warp-u ----
    {
        const int tx = lane;
#pragma unroll
        for (int c4 = 0; c4 < 4; c4++) {
            float4 maq[2][4];
#pragma unroll
            for (int cc = 0; cc < 2; cc++) {
                int m = c4*64 + tx + 32*cc;
                const float4* p = (const float4*)(Ma + ((size_t)m*U_ + u)*D_);
#pragma unroll
                for (int dq = 0; dq < 4; dq++) maq[cc][dq] = p[dq];
            }
            ull acc[4][2];
#pragma unroll
            for (int bp = 0; bp < 4; bp++) { acc[bp][0] = 0ull; acc[bp][1] = 0ull; }

#pragma unroll
            for (int d = 0; d < 16; d++) {
                ull ap[4];
                F4U t0; t0.f = *(const float4*)(&sA[wu*SA_UP + d*8]);
                F4U t1; t1.f = *(const float4*)(&sA[wu*SA_UP + d*8 + 4]);
                ap[0] = t0.p[0]; ap[1] = t0.p[1];
                ap[2] = t1.p[0]; ap[3] = t1.p[1];
                F4U mq0; mq0.f = maq[0][d>>2];
                F4U mq1; mq1.f = maq[1][d>>2];
                ull md0 = pk2(mq0.s[d & 3], mq0.s[d & 3]);
                ull md1 = pk2(mq1.s[d & 3], mq1.s[d & 3]);
#pragma unroll
                for (int bp = 0; bp < 4; bp++) {
                    ffma2(acc[bp][0], ap[bp], md0);
                    ffma2(acc[bp][1], ap[bp], md1);
                }
            }
#pragma unroll
            for (int cc = 0; cc < 2; cc++) {
                int m = c4*64 + tx + 32*cc;
#pragma unroll
                for (int bp = 0; bp < 4; bp++) {
                    float s0, s1;
                    upk2(acc[bp][cc], s0, s1);
                    int bA = 2*bp, bB = 2*bp + 1;
                    sS[(bA*NU + wu)*SP + m] = (m == b0 + bA) ? -INFINITY : s0 * tu;
                    sS[(bB*NU + wu)*SP + m] = (m == b0 + bB) ? -INFINITY : s1 * tu;
                }
            }
        }
    }
    __syncthreads();

    // ---- stage 2: grouped softmax over m within (b,u,m%8), /8 ----
    {
        int g  = tid & 7;
        int uu = (tid >> 3) & 7;
        int bq = tid >> 6;                 // 0..3
#pragma unroll
        for (int i = 0; i < 2; i++) {
            int b = bq + 4*i;
            float* row = sS + (b*NU + uu)*SP + g;
            float v[32];
            float mx = -INFINITY;
#pragma unroll
            for (int j = 0; j < 32; j++) { v[j] = row[j*8]; mx = fmaxf(mx, v[j]); }
            float s = 0.f;
#pragma unroll
            for (int j = 0; j < 32; j++) { v[j] = __expf(v[j] - mx); s += v[j]; }
            float inv = 1.f / (8.f * s);
#pragma unroll
            for (int j = 0; j < 32; j++) row[j*8] = v[j] * inv;
        }
    }
    __syncthreads();

    // ---- stage 2b: weights store [b][m][u0..u0+7] (32B sectors) ----
    {
        int b  = tid >> 5;                 // 0..7
        int tl = tid & 31;
#pragma unroll
        for (int mi = 0; mi < 8; mi++) {
            int m = tl + 32*mi;
            float w8[8];
#pragma unroll
            for (int uu = 0; uu < 8; uu++) w8[uu] = sS[(b*NU + uu)*SP + m];
            float4* dst = (float4*)(wout + ((size_t)(b0 + b)*M_ + m)*U_ + u0);
            dst[0] = make_float4(w8[0], w8[1], w8[2], w8[3]);
            dst[1] = make_float4(w8[4], w8[5], w8[6], w8[7]);
        }
    }

    // ---- stage 3: outputs O[8b,16d] per warp-u ----
    {
        const int mseg = lane & 7;
        const int dg   = (lane >> 3) & 1;
        const int bg   = lane >> 4;        // 0..1 -> b = bg*4 + bi

        ull acc[4][4];
#pragma unroll
        for (int bi = 0; bi < 4; bi++)
#pragma unroll
            for (int dp = 0; dp < 4; dp++) acc[bi][dp] = 0ull;

#pragma unroll
        for (int c4 = 0; c4 < 4; c4++) {
            __syncthreads();
#pragma unroll
            for (int t = 0; t < 8; t++) {
                int idx = tid + t*256;
                int mloc = idx >> 5;       // 0..63
                int uu = (idx >> 2) & 7;
                int dq = idx & 3;
                float4 v = *(const float4*)(Mv + ((size_t)(c4*64 + mloc)*U_ + u0+uu)*D_ + dq*4);
                sMv4[uu*256 + mloc*4 + (dq ^ ((mloc >> 3) & 3))] = v;
            }
            __syncthreads();

#pragma unroll
            for (int h = 0; h < 2; h++) {
                int mbase = c4*64 + mseg*8 + h*4;
                F4U w4[4];
#pragma unroll
                for (int bi = 0; bi < 4; bi++)
                    w4[bi].f = *(const float4*)(&sS[((bg*4 + bi)*NU + wu)*SP + mbase]);
                ull mvp[4][4];
#pragma unroll
                for (int mi = 0; mi < 4; mi++) {
#pragma unroll
                    for (int k = 0; k < 2; k++) {
                        int mloc = mseg*8 + h*4 + mi;
                        F4U v; v.f = sMv4[wu*256 + mloc*4 + ((dg*2 + k) ^ (mseg & 3))];
                        mvp[mi][k*2]   = v.p[0];
                        mvp[mi][k*2+1] = v.p[1];
                    }
                }
#pragma unroll
                for (int mi = 0; mi < 4; mi++)
#pragma unroll
                    for (int bi = 0; bi < 4; bi++) {
                        ull wd = pk2(w4[bi].s[mi], w4[bi].s[mi]);
                        ffma2(acc[bi][0], wd, mvp[mi][0]);
                        ffma2(acc[bi][1], wd, mvp[mi][1]);
                        ffma2(acc[bi][2], wd, mvp[mi][2]);
                        ffma2(acc[bi][3], wd, mvp[mi][3]);
                    }
            }
        }

        // reduce over mseg (lane bits 0..2)
#pragma unroll
        for (int off = 1; off < 8; off <<= 1) {
#pragma unroll
            for (int bi = 0; bi < 4; bi++)
#pragma unroll
                for (int dp = 0; dp < 4; dp++) {
                    ull o = __shfl_xor_sync(0xffffffffu, acc[bi][dp], off);
                    acc[bi][dp] = add2(acc[bi][dp], o);
                }
        }
        if (mseg == 0) {
#pragma unroll
            for (int bi = 0; bi < 4; bi++) {
                float o[8];
                upk2(acc[bi][0], o[0], o[1]);
                upk2(acc[bi][1], o[2], o[3]);
                upk2(acc[bi][2], o[4], o[5]);
                upk2(acc[bi][3], o[6], o[7]);
                float* dst = outp + ((size_t)(b0 + bg*4 + bi)*U_ + u)*D_ + dg*8;
                *(float4*)(dst)     = make_float4(o[0], o[1], o[2], o[3]);
                *(float4*)(dst + 4) = make_float4(o[4], o[5], o[6], o[7]);
            }
        }
    }
}

// ---------------------------------------------------------------------------
extern "C" void kernel_launch(void* const* d_in, const int* in_sizes, int n_in,
                              void* d_out, int out_size)
{
    const float* x    = (const float*)d_in[0];
    const float* W1   = (const float*)d_in[1];
    const float* b1   = (const float*)d_in[2];
    const float* W2   = (const float*)d_in[3];
    const float* b2   = (const float*)d_in[4];
    const float* temp = (const float*)d_in[5];
    const float* Ma   = (const float*)d_in[6];
    const float* Mv   = (const float*)d_in[7];

    float* attn = (float*)d_out;                         // [B,U,D]
    float* wout = attn + (size_t)B_ * U_ * D_;           // [B,M,U]
    float* outp = wout + (size_t)B_ * B_ * U_;           // [B,U,D]

    float* h_ptr = nullptr;
    cudaGetSymbolAddress((void**)&h_ptr, g_h);
    float* hp_ptr = nullptr;
    cudaGetSymbolAddress((void**)&hp_ptr, g_hp);
    float* ap_ptr = nullptr;
    cudaGetSymbolAddress((void**)&ap_ptr, g_ap);

    // h partials: x @ W1 split-K=4
    sgemm_core<64, 32, 16, 4, 4, 128, false>
        <<<dim3(DG_/32, B_/64, KSPLIT1), 128>>>(
        x, W1, nullptr, hp_ptr, DG_, DIN_, DIN_/KSPLIT1, B_*DG_);
    reduce_h<<<(B_*DG_/4)/256, 256>>>(b1);

    // attention partials: h @ W2 split-K=2  (TM=16,TN=4; TX*TY=16*8=128)
    sgemm_core<128, 64, 16, 16, 4, 128, false>
        <<<dim3((U_*D_)/64, B_/128, KSPLIT2), 128>>>(
        h_ptr, W2, nullptr, ap_ptr, U_*D_, DG_, DG_/KSPLIT2, B_*U_*D_);
    reduce_att<<<(B_*U_*D_/4)/256, 256>>>(b2, attn);

    // fused scores + softmax + weights + outputs  (2 CTAs/SM)
    int smem = SM_FLOATS * (int)sizeof(float);
    cudaFuncSetAttribute(fused_attn,
                         cudaFuncAttributeMaxDynamicSharedMemorySize, smem);
    fused_attn<<<dim3(B_/NB, U_/NU), 256, smem>>>(attn, Ma, Mv, temp, wout, outp);
}

// round 7
// speedup vs baseline: 1.0468x; 1.0468x over previous
#include <cuda_runtime.h>
#include <cmath>

#define B_   256
#define DIN_ 1024
#define DG_  1024
#define U_   512
#define D_   16
#define M_   256
#define G_   8

#define NB 16     // b per fused block
#define NU 8      // u per fused block
#define SP 264    // S row pitch (floats)
#define SA_UP 260 // per-u sA pitch: 16d*16b + 4 pad

#define KSPLIT1 4

__device__ float g_h[B_ * DG_];               // 1 MB: h
__device__ float g_hp[KSPLIT1][B_ * DG_];     // 4 MB: GEMM1 split-K partials

// ---------------------------------------------------------------------------
// f32x2 helpers
// ---------------------------------------------------------------------------
typedef unsigned long long ull;
union F4U { float4 f; ull p[2]; float s[4]; };

__device__ __forceinline__ ull pk2(float a, float b) {
    ull r; asm("mov.b64 %0, {%1, %2};" : "=l"(r) : "f"(a), "f"(b)); return r;
}
__device__ __forceinline__ void upk2(ull v, float& a, float& b) {
    asm("mov.b64 {%0, %1}, %2;" : "=f"(a), "=f"(b) : "l"(v));
}
__device__ __forceinline__ void ffma2(ull& d, ull a, ull b) {
    asm("fma.rn.f32x2 %0, %1, %2, %0;" : "+l"(d) : "l"(a), "l"(b));
}
__device__ __forceinline__ ull add2(ull a, ull b) {
    ull r; asm("add.rn.f32x2 %0, %1, %2;" : "=l"(r) : "l"(a), "l"(b)); return r;
}

// ---------------------------------------------------------------------------
// fp32 SGEMM core, packed-pair inner product, optional bias, k-range slice.
// ---------------------------------------------------------------------------
template<int BM, int BN, int BK, int TM, int TN, int THREADS, bool BIAS>
__global__ void __launch_bounds__(THREADS) sgemm_core(
        const float* __restrict__ A, const float* __restrict__ Bm,
        const float* __restrict__ bias, float* __restrict__ C,
        int N, int K, int kChunk, int sliceStride)
{
    static_assert((BN / TN) * (BM / TM) == THREADS, "thread tiling mismatch");
    __shared__ float As[BK][BM + 4];
    __shared__ float Bs[BK][BN];

    const int tid = threadIdx.x;
    const int bx = blockIdx.x, by = blockIdx.y;
    const int kBegin = blockIdx.z * kChunk;
    const int kEnd   = kBegin + kChunk;
    float* Cs = C + (size_t)blockIdx.z * sliceStride;

    constexpr int TX = BN / TN;
    const int tx = tid % TX;
    const int ty = tid / TX;

    constexpr int LA = (BM * BK / 4) / THREADS;
    constexpr int LB = (BK * BN / 4) / THREADS;
    static_assert(LA >= 1 && LB >= 1, "tile too small");

    ull acc2[TM / 2][TN];
#pragma unroll
    for (int r = 0; r < TM / 2; r++)
#pragma unroll
        for (int c = 0; c < TN; c++) acc2[r][c] = 0ull;

    const float* Ablk = A + (size_t)by * BM * K;
    const float* Bblk = Bm + (size_t)bx * BN;

#pragma unroll
    for (int i = 0; i < LA; i++) {
        int a = tid + i * THREADS;
        int row = a / (BK / 4), kq = a % (BK / 4);
        float4 v = *(const float4*)(Ablk + (size_t)row * K + kBegin + kq * 4);
        As[kq*4+0][row] = v.x; As[kq*4+1][row] = v.y;
        As[kq*4+2][row] = v.z; As[kq*4+3][row] = v.w;
    }
#pragma unroll
    for (int i = 0; i < LB; i++) {
        int b = tid + i * THREADS;
        int kr = b / (BN / 4), nq = b % (BN / 4);
        *(float4*)(&Bs[kr][nq*4]) =
            *(const float4*)(Bblk + (size_t)(kBegin + kr) * N + nq * 4);
    }
    __syncthreads();

    for (int k0 = kBegin; k0 < kEnd; k0 += BK) {
        float4 nA[LA], nB[LB];
        const bool more = (k0 + BK) < kEnd;
        if (more) {
#pragma unroll
            for (int i = 0; i < LA; i++) {
                int a = tid + i * THREADS;
                int row = a / (BK / 4), kq = a % (BK / 4);
                nA[i] = *(const float4*)(Ablk + (size_t)row * K + k0 + BK + kq * 4);
            }
#pragma unroll
            for (int i = 0; i < LB; i++) {
                int b = tid + i * THREADS;
                int kr = b / (BN / 4), nq = b % (BN / 4);
                nB[i] = *(const float4*)(Bblk + (size_t)(k0 + BK + kr) * N + nq * 4);
            }
        }

#pragma unroll
        for (int k = 0; k < BK; k++) {
            ull ap[TM / 2];
#pragma unroll
            for (int q = 0; q < TM / 4; q++) {
                F4U t; t.f = *(const float4*)(&As[k][ty*TM + q*4]);
                ap[2*q]   = t.p[0];
                ap[2*q+1] = t.p[1];
            }
            ull bd[TN];
#pragma unroll
            for (int q = 0; q < TN / 4; q++) {
                float4 v = *(const float4*)(&Bs[k][tx*TN + q*4]);
                bd[q*4+0] = pk2(v.x, v.x); bd[q*4+1] = pk2(v.y, v.y);
                bd[q*4+2] = pk2(v.z, v.z); bd[q*4+3] = pk2(v.w, v.w);
            }
#pragma unroll
            for (int r = 0; r < TM / 2; r++)
#pragma unroll
                for (int c = 0; c < TN; c++)
                    ffma2(acc2[r][c], ap[r], bd[c]);
        }

        if (more) {
            __syncthreads();
#pragma unroll
            for (int i = 0; i < LA; i++) {
                int a = tid + i * THREADS;
                int row = a / (BK / 4), kq = a % (BK / 4);
                As[kq*4+0][row] = nA[i].x; As[kq*4+1][row] = nA[i].y;
                As[kq*4+2][row] = nA[i].z; As[kq*4+3][row] = nA[i].w;
            }
#pragma unroll
            for (int i = 0; i < LB; i++) {
                int b = tid + i * THREADS;
                int kr = b / (BN / 4), nq = b % (BN / 4);
                *(float4*)(&Bs[kr][nq*4]) = nB[i];
            }
            __syncthreads();
        }
    }

#pragma unroll
    for (int r2 = 0; r2 < TM / 2; r2++) {
        float s[2][TN];
#pragma unroll
        for (int c = 0; c < TN; c++) upk2(acc2[r2][c], s[0][c], s[1][c]);
#pragma unroll
        for (int h = 0; h < 2; h++) {
            int row = by*BM + ty*TM + 2*r2 + h;
#pragma unroll
            for (int c = 0; c < TN; c += 4) {
                int col = bx*BN + tx*TN + c;
                float4 v;
                if (BIAS) {
                    v.x = s[h][c+0] + bias[col+0];
                    v.y = s[h][c+1] + bias[col+1];
                    v.z = s[h][c+2] + bias[col+2];
                    v.w = s[h][c+3] + bias[col+3];
                } else {
                    v.x = s[h][c+0]; v.y = s[h][c+1];
                    v.z = s[h][c+2]; v.w = s[h][c+3];
                }
                *(float4*)(Cs + (size_t)row * N + col) = v;
            }
        }
    }
}

// ---------------------------------------------------------------------------
// reduce GEMM1 split-K partials + bias -> g_h
// ---------------------------------------------------------------------------
__global__ void __launch_bounds__(256) reduce_h(const float* __restrict__ bias)
{
    int i = blockIdx.x * 256 + threadIdx.x;
    int col4 = i & (DG_/4 - 1);
    float4 a = *(const float4*)(&g_hp[0][i*4]);
    float4 b = *(const float4*)(&g_hp[1][i*4]);
    float4 c = *(const float4*)(&g_hp[2][i*4]);
    float4 d = *(const float4*)(&g_hp[3][i*4]);
    float4 bb = *(const float4*)(bias + col4*4);
    float4 o;
    o.x = a.x + b.x + c.x + d.x + bb.x;
    o.y = a.y + b.y + c.y + d.y + bb.y;
    o.z = a.z + b.z + c.z + d.z + bb.z;
    o.w = a.w + b.w + c.w + d.w + bb.w;
    *(float4*)(&g_h[i*4]) = o;
}

// ---------------------------------------------------------------------------
// Fused v4: block = (16 b, 8 u), 512 threads, full m=256 resident.
//   stage1: warp = (u, m-half): S[16b, 128m]
//   stage3: warp = (u, b-half): O[8b, 16d]
// ---------------------------------------------------------------------------
#define SM_FLOATS (NB*NU*SP + NU*SA_UP + NU*64*16)

__global__ void __launch_bounds__(512) fused_attn(
        const float* __restrict__ attn,   // [B,U,D]
        const float* __restrict__ Ma,     // [M,U,D]
        const float* __restrict__ Mv,     // [M,U,D]
        const float* __restrict__ temp,   // [U]
        float* __restrict__ wout,         // [B,M,U]
        float* __restrict__ outp)         // [B,U,D]
{
    extern __shared__ float sm[];
    float*  sS   = sm;                        // 128 rows (b*8+u) x 264
    float*  sA   = sS + NB*NU*SP;             // [u]: pitch 260, inside [d][b16]
    float4* sMv4 = (float4*)(sA + NU*SA_UP);  // [u][64m x 4] swizzled chunk

    const int b0  = blockIdx.x * NB;
    const int u0  = blockIdx.y * NU;
    const int tid = threadIdx.x;
    const int lane = tid & 31;
    const int wid  = tid >> 5;        // 0..15
    const int uu   = wid & 7;         // warp's u
    const int u    = u0 + uu;

    // ---- stage attn tile -> sA[u][d][b16]  (2048 floats, 1 float4/thread) ----
    {
        int bi  = tid >> 5;           // 0..15
        int uu2 = (tid >> 2) & 7;
        int dq  = tid & 3;
        float4 v = *(const float4*)(attn + ((size_t)(b0+bi)*U_ + u0+uu2)*D_ + dq*4);
        sA[uu2*SA_UP + (dq*4+0)*16 + bi] = v.x;
        sA[uu2*SA_UP + (dq*4+1)*16 + bi] = v.y;
        sA[uu2*SA_UP + (dq*4+2)*16 + bi] = v.z;
        sA[uu2*SA_UP + (dq*4+3)*16 + bi] = v.w;
    }
    const float tu = temp[u];
    __syncthreads();

    // ---- stage 1: warp (uu, mh) computes S[16b, 128m] ----
    {
        const int mh = wid >> 3;      // m-half 0/1
#pragma unroll
        for (int cc4 = 0; cc4 < 2; cc4++) {       // 2 chunks of 64 m
            const int mBase = mh*128 + cc4*64;
            float4 maq[2][4];
#pragma unroll
            for (int cc = 0; cc < 2; cc++) {
                int m = mBase + lane + 32*cc;
                const float4* p = (const float4*)(Ma + ((size_t)m*U_ + u)*D_);
#pragma unroll
                for (int dq = 0; dq < 4; dq++) maq[cc][dq] = p[dq];
            }
            ull acc[8][2];
#pragma unroll
            for (int bp = 0; bp < 8; bp++) { acc[bp][0] = 0ull; acc[bp][1] = 0ull; }

#pragma unroll
            for (int d = 0; d < 16; d++) {
                ull ap[8];
#pragma unroll
                for (int q = 0; q < 4; q++) {
                    F4U t; t.f = *(const float4*)(&sA[uu*SA_UP + d*16 + q*4]);
                    ap[2*q]   = t.p[0];
                    ap[2*q+1] = t.p[1];
                }
                F4U mq0; mq0.f = maq[0][d>>2];
                F4U mq1; mq1.f = maq[1][d>>2];
                ull md0 = pk2(mq0.s[d & 3], mq0.s[d & 3]);
                ull md1 = pk2(mq1.s[d & 3], mq1.s[d & 3]);
#pragma unroll
                for (int bp = 0; bp < 8; bp++) {
                    ffma2(acc[bp][0], ap[bp], md0);
                    ffma2(acc[bp][1], ap[bp], md1);
                }
            }
#pragma unroll
            for (int cc = 0; cc < 2; cc++) {
                int m = mBase + lane + 32*cc;
#pragma unroll
                for (int bp = 0; bp < 8; bp++) {
                    float s0, s1;
                    upk2(acc[bp][cc], s0, s1);
                    int bA = 2*bp, bB = 2*bp + 1;
                    sS[(bA*NU + uu)*SP + m] = (m == b0 + bA) ? -INFINITY : s0 * tu;
                    sS[(bB*NU + uu)*SP + m] = (m == b0 + bB) ? -INFINITY : s1 * tu;
                }
            }
        }
    }
    __syncthreads();

    // ---- stage 2: grouped softmax over m within (b,u,m%8), /8 ----
    {
        int g   = tid & 7;
        int uu3 = (tid >> 3) & 7;
        int bq  = tid >> 6;                // 0..7
#pragma unroll
        for (int i = 0; i < 2; i++) {
            int b = bq + 8*i;
            float* row = sS + (b*NU + uu3)*SP + g;
            float v[32];
            float mx = -INFINITY;
#pragma unroll
            for (int j = 0; j < 32; j++) { v[j] = row[j*8]; mx = fmaxf(mx, v[j]); }
            float s = 0.f;
#pragma unroll
            for (int j = 0; j < 32; j++) { v[j] = __expf(v[j] - mx); s += v[j]; }
            float inv = 1.f / (8.f * s);
#pragma unroll
            for (int j = 0; j < 32; j++) row[j*8] = v[j] * inv;
        }
    }
    __syncthreads();

    // ---- stage 2b: weights store [b][m][u0..u0+7] (32B sectors) ----
    {
        int b  = tid >> 5;                 // 0..15
        int tl = lane;
#pragma unroll
        for (int mi = 0; mi < 8; mi++) {
            int m = tl + 32*mi;
            float w8[8];
#pragma unroll
            for (int uw = 0; uw < 8; uw++) w8[uw] = sS[(b*NU + uw)*SP + m];
            float4* dst = (float4*)(wout + ((size_t)(b0 + b)*M_ + m)*U_ + u0);
            dst[0] = make_float4(w8[0], w8[1], w8[2], w8[3]);
            dst[1] = make_float4(w8[4], w8[5], w8[6], w8[7]);
        }
    }

    // ---- stage 3: warp (uu, bh) computes O[8b, 16d] ----
    {
        const int bh   = wid >> 3;         // b-half 0/1
        const int mseg = lane & 7;
        const int dg   = (lane >> 3) & 1;
        const int bg   = lane >> 4;        // 0..1

        ull acc[4][4];
#pragma unroll
        for (int bi = 0; bi < 4; bi++)
#pragma unroll
            for (int dp = 0; dp < 4; dp++) acc[bi][dp] = 0ull;

#pragma unroll
        for (int c4 = 0; c4 < 4; c4++) {
            __syncthreads();
#pragma unroll
            for (int t = 0; t < 4; t++) {
                int idx = tid + t*512;
                int mloc = idx >> 5;       // 0..63
                int uw = (idx >> 2) & 7;
                int dq = idx & 3;
                float4 v = *(const float4*)(Mv + ((size_t)(c4*64 + mloc)*U_ + u0+uw)*D_ + dq*4);
                sMv4[uw*256 + mloc*4 + (dq ^ ((mloc >> 3) & 3))] = v;
            }
            __syncthreads();

#pragma unroll
            for (int h = 0; h < 2; h++) {
                int mbase = c4*64 + mseg*8 + h*4;
                F4U w4[4];
#pragma unroll
                for (int bi = 0; bi < 4; bi++) {
                    int b = bh*8 + bg*4 + bi;
                    w4[bi].f = *(const float4*)(&sS[(b*NU + uu)*SP + mbase]);
                }
                ull mvp[4][4];
#pragma unroll
                for (int mi = 0; mi < 4; mi++) {
#pragma unroll
                    for (int k = 0; k < 2; k++) {
                        int mloc = mseg*8 + h*4 + mi;
                        F4U v; v.f = sMv4[uu*256 + mloc*4 + ((dg*2 + k) ^ (mseg & 3))];
                        mvp[mi][k*2]   = v.p[0];
                        mvp[mi][k*2+1] = v.p[1];
                    }
                }
#pragma unroll
                for (int mi = 0; mi < 4; mi++)
#pragma unroll
                    for (int bi = 0; bi < 4; bi++) {
                        ull wd = pk2(w4[bi].s[mi], w4[bi].s[mi]);
                        ffma2(acc[bi][0], wd, mvp[mi][0]);
                        ffma2(acc[bi][1], wd, mvp[mi][1]);
                        ffma2(acc[bi][2], wd, mvp[mi][2]);
                        ffma2(acc[bi][3], wd, mvp[mi][3]);
                    }
            }
        }

        // reduce over mseg (lane bits 0..2)
#pragma unroll
        for (int off = 1; off < 8; off <<= 1) {
#pragma unroll
            for (int bi = 0; bi < 4; bi++)
#pragma unroll
                for (int dp = 0; dp < 4; dp++) {
                    ull o = __shfl_xor_sync(0xffffffffu, acc[bi][dp], off);
                    acc[bi][dp] = add2(acc[bi][dp], o);
                }
        }
        if (mseg == 0) {
#pragma unroll
            for (int bi = 0; bi < 4; bi++) {
                float o[8];
                upk2(acc[bi][0], o[0], o[1]);
                upk2(acc[bi][1], o[2], o[3]);
                upk2(acc[bi][2], o[4], o[5]);
                upk2(acc[bi][3], o[6], o[7]);
                int b = bh*8 + bg*4 + bi;
                float* dst = outp + ((size_t)(b0 + b)*U_ + u)*D_ + dg*8;
                *(float4*)(dst)     = make_float4(o[0], o[1], o[2], o[3]);
                *(float4*)(dst + 4) = make_float4(o[4], o[5], o[6], o[7]);
            }
        }
    }
}

// ---------------------------------------------------------------------------
extern "C" void kernel_launch(void* const* d_in, const int* in_sizes, int n_in,
                              void* d_out, int out_size)
{
    const float* x    = (const float*)d_in[0];
    const float* W1   = (const float*)d_in[1];
    const float* b1   = (const float*)d_in[2];
    const float* W2   = (const float*)d_in[3];
    const float* b2   = (const float*)d_in[4];
    const float* temp = (const float*)d_in[5];
    const float* Ma   = (const float*)d_in[6];
    const float* Mv   = (const float*)d_in[7];

    float* attn = (float*)d_out;                         // [B,U,D]
    float* wout = attn + (size_t)B_ * U_ * D_;           // [B,M,U]
    float* outp = wout + (size_t)B_ * B_ * U_;           // [B,U,D]

    float* h_ptr = nullptr;
    cudaGetSymbolAddress((void**)&h_ptr, g_h);
    float* hp_ptr = nullptr;
    cudaGetSymbolAddress((void**)&hp_ptr, g_hp);

    // h partials: x @ W1 split-K=4, then reduce+bias
    sgemm_core<64, 32, 16, 4, 4, 128, false>
        <<<dim3(DG_/32, B_/64, KSPLIT1), 128>>>(
        x, W1, nullptr, hp_ptr, DG_, DIN_, DIN_/KSPLIT1, B_*DG_);
    reduce_h<<<(B_*DG_/4)/256, 256>>>(b1);

    // attention = h @ W2 + b2  (512 blocks of 128 threads; TX*TY=16*8=128)
    sgemm_core<64, 64, 16, 8, 4, 128, true>
        <<<dim3((U_*D_)/64, B_/64, 1), 128>>>(
        h_ptr, W2, b2, attn, U_*D_, DG_, DG_, 0);

    // fused scores + softmax + weights + outputs  (512 threads, 16 warps/SM)
    int smem = SM_FLOATS * (int)sizeof(float);
    cudaFuncSetAttribute(fused_attn,
                         cudaFuncAttributeMaxDynamicSharedMemorySize, smem);
    fused_attn<<<dim3(B_/NB, U_/NU), 512, smem>>>(attn, Ma, Mv, temp, wout, outp);
}

// round 9
// speedup vs baseline: 1.3152x; 1.2565x over previous
#include <cuda_runtime.h>
#include <cuda_bf16.h>
#include <cmath>

#define B_   256
#define DIN_ 1024
#define DG_  1024
#define U_   512
#define D_   16
#define M_   256
#define G_   8

#define NB 16
#define NU 8
#define SP 264

__device__ float g_h[B_ * DG_];
__device__ float g_hp[4][B_ * DG_];
__device__ __nv_bfloat16 g_hh[B_ * DG_];
__device__ __nv_bfloat16 g_hl[B_ * DG_];
__device__ __nv_bfloat16 g_w2h[8192 * 1024];
__device__ __nv_bfloat16 g_w2l[8192 * 1024];

typedef unsigned long long ull;
union F4U { float4 f; ull p[2]; float s[4]; };
union BFQ { uint2 u; __nv_bfloat16 h[4]; };

__device__ __forceinline__ ull pk2(float a, float b) {
    ull r; asm("mov.b64 %0, {%1, %2};" : "=l"(r) : "f"(a), "f"(b)); return r;
}
__device__ __forceinline__ void upk2(ull v, float& a, float& b) {
    asm("mov.b64 {%0, %1}, %2;" : "=f"(a), "=f"(b) : "l"(v));
}
__device__ __forceinline__ void ffma2(ull& d, ull a, ull b) {
    asm("fma.rn.f32x2 %0, %1, %2, %0;" : "+l"(d) : "l"(a), "l"(b));
}
__device__ __forceinline__ ull add2(ull a, ull b) {
    ull r; asm("add.rn.f32x2 %0, %1, %2;" : "=l"(r) : "l"(a), "l"(b)); return r;
}
__device__ __forceinline__ void ldsm4(unsigned* r, unsigned addr) {
    asm volatile("ldmatrix.sync.aligned.m8n8.x4.shared.b16 {%0,%1,%2,%3}, [%4];"
        : "=r"(r[0]), "=r"(r[1]), "=r"(r[2]), "=r"(r[3]) : "r"(addr));
}
__device__ __forceinline__ void ldsm2(unsigned* r, unsigned addr) {
    asm volatile("ldmatrix.sync.aligned.m8n8.x2.shared.b16 {%0,%1}, [%2];"
        : "=r"(r[0]), "=r"(r[1]) : "r"(addr));
}
__device__ __forceinline__ void mma16816(float* d, const unsigned* a, const unsigned* b) {
    asm volatile(
        "mma.sync.aligned.m16n8k16.row.col.f32.bf16.bf16.f32 "
        "{%0,%1,%2,%3}, {%4,%5,%6,%7}, {%8,%9}, {%0,%1,%2,%3};"
        : "+f"(d[0]), "+f"(d[1]), "+f"(d[2]), "+f"(d[3])
        : "r"(a[0]), "r"(a[1]), "r"(a[2]), "r"(a[3]), "r"(b[0]), "r"(b[1]));
}

// ---------------------------------------------------------------------------
// GEMM1 partials: g_hp[z][64-row tile][32-col tile] = x @ W1 (k-slice of 256)
// ---------------------------------------------------------------------------
__global__ void __launch_bounds__(128) gemm1_partial(
        const float* __restrict__ A, const float* __restrict__ Bm)
{
    __shared__ float As[16][68];
    __shared__ float Bs[16][32];

    const int tid = threadIdx.x;
    const int bx = blockIdx.x, by = blockIdx.y, bz = blockIdx.z;
    const int kBegin = bz * 256;
    const int tx = tid & 7;
    const int ty = tid >> 3;

    ull acc2[2][4];
    acc2[0][0]=0ull; acc2[0][1]=0ull; acc2[0][2]=0ull; acc2[0][3]=0ull;
    acc2[1][0]=0ull; acc2[1][1]=0ull; acc2[1][2]=0ull; acc2[1][3]=0ull;

    const float* Ablk = A + (size_t)by * 64 * 1024;
    const float* Bblk = Bm + bx * 32;

    const int ar = tid >> 2;     // 0..31
    const int akq = tid & 3;     // 0..3
    const int bkr = tid >> 3;    // 0..15
    const int bnq = tid & 7;     // 0..7

    {
        float4 v0 = *(const float4*)(Ablk + (size_t)ar * 1024 + kBegin + akq * 4);
        As[akq*4+0][ar] = v0.x; As[akq*4+1][ar] = v0.y;
        As[akq*4+2][ar] = v0.z; As[akq*4+3][ar] = v0.w;
        float4 v1 = *(const float4*)(Ablk + (size_t)(ar+32) * 1024 + kBegin + akq * 4);
        As[akq*4+0][ar+32] = v1.x; As[akq*4+1][ar+32] = v1.y;
        As[akq*4+2][ar+32] = v1.z; As[akq*4+3][ar+32] = v1.w;
        float4 vb = *(const float4*)(Bblk + (size_t)(kBegin + bkr) * 1024 + bnq * 4);
        *(float4*)(&Bs[bkr][bnq*4]) = vb;
    }
    __syncthreads();

    for (int k0 = kBegin; k0 < kBegin + 256; k0 += 16) {
        const bool more = (k0 + 16) < (kBegin + 256);
        float4 nA0, nA1, nB0;
        if (more) {
            nA0 = *(const float4*)(Ablk + (size_t)ar * 1024 + k0 + 16 + akq * 4);
            nA1 = *(const float4*)(Ablk + (size_t)(ar+32) * 1024 + k0 + 16 + akq * 4);
            nB0 = *(const float4*)(Bblk + (size_t)(k0 + 16 + bkr) * 1024 + bnq * 4);
        }

#pragma unroll
        for (int k = 0; k < 16; k++) {
            F4U ta; ta.f = *(const float4*)(&As[k][ty*4]);
            float4 vb = *(const float4*)(&Bs[k][tx*4]);
            ull bd0 = pk2(vb.x, vb.x);
            ull bd1 = pk2(vb.y, vb.y);
            ull bd2 = pk2(vb.z, vb.z);
            ull bd3 = pk2(vb.w, vb.w);
            ffma2(acc2[0][0], ta.p[0], bd0);
            ffma2(acc2[0][1], ta.p[0], bd1);
            ffma2(acc2[0][2], ta.p[0], bd2);
            ffma2(acc2[0][3], ta.p[0], bd3);
            ffma2(acc2[1][0], ta.p[1], bd0);
            ffma2(acc2[1][1], ta.p[1], bd1);
            ffma2(acc2[1][2], ta.p[1], bd2);
            ffma2(acc2[1][3], ta.p[1], bd3);
        }

        if (more) {
            __syncthreads();
            As[akq*4+0][ar] = nA0.x; As[akq*4+1][ar] = nA0.y;
            As[akq*4+2][ar] = nA0.z; As[akq*4+3][ar] = nA0.w;
            As[akq*4+0][ar+32] = nA1.x; As[akq*4+1][ar+32] = nA1.y;
            As[akq*4+2][ar+32] = nA1.z; As[akq*4+3][ar+32] = nA1.w;
            *(float4*)(&Bs[bkr][bnq*4]) = nB0;
            __syncthreads();
        }
    }

    float* Cs = &g_hp[bz][0];
#pragma unroll
    for (int r2 = 0; r2 < 2; r2++) {
        float s0[4], s1[4];
        upk2(acc2[r2][0], s0[0], s1[0]);
        upk2(acc2[r2][1], s0[1], s1[1]);
        upk2(acc2[r2][2], s0[2], s1[2]);
        upk2(acc2[r2][3], s0[3], s1[3]);
        int row0 = by*64 + ty*4 + 2*r2;
        int col = bx*32 + tx*4;
        *(float4*)(Cs + (size_t)row0 * 1024 + col) =
            make_float4(s0[0], s0[1], s0[2], s0[3]);
        *(float4*)(Cs + (size_t)(row0 + 1) * 1024 + col) =
            make_float4(s1[0], s1[1], s1[2], s1[3]);
    }
}

// ---------------------------------------------------------------------------
// reduce GEMM1 partials + bias -> g_h (fp32) and bf16 hi/lo planes
// ---------------------------------------------------------------------------
__global__ void __launch_bounds__(256) reduce_bias_h(const float* __restrict__ bias)
{
    int i = blockIdx.x * 256 + threadIdx.x;
    int col4 = i & 255;
    float4 a = *(const float4*)(&g_hp[0][i*4]);
    float4 b = *(const float4*)(&g_hp[1][i*4]);
    float4 c = *(const float4*)(&g_hp[2][i*4]);
    float4 d = *(const float4*)(&g_hp[3][i*4]);
    float4 bb = *(const float4*)(bias + col4*4);
    float4 o;
    o.x = a.x + b.x + c.x + d.x + bb.x;
    o.y = a.y + b.y + c.y + d.y + bb.y;
    o.z = a.z + b.z + c.z + d.z + bb.z;
    o.w = a.w + b.w + c.w + d.w + bb.w;
    *(float4*)(&g_h[i*4]) = o;

    BFQ hi, lo;
    float v0 = o.x, v1 = o.y, v2 = o.z, v3 = o.w;
    hi.h[0] = __float2bfloat16(v0);
    hi.h[1] = __float2bfloat16(v1);
    hi.h[2] = __float2bfloat16(v2);
    hi.h[3] = __float2bfloat16(v3);
    lo.h[0] = __float2bfloat16(v0 - __bfloat162float(hi.h[0]));
    lo.h[1] = __float2bfloat16(v1 - __bfloat162float(hi.h[1]));
    lo.h[2] = __float2bfloat16(v2 - __bfloat162float(hi.h[2]));
    lo.h[3] = __float2bfloat16(v3 - __bfloat162float(hi.h[3]));
    *(uint2*)(&g_hh[i*4]) = hi.u;
    *(uint2*)(&g_hl[i*4]) = lo.u;
}

// ---------------------------------------------------------------------------
// W2 [k=1024][n=8192] fp32 -> transposed bf16 hi/lo planes [n][k]
// ---------------------------------------------------------------------------
__global__ void __launch_bounds__(256) w2conv_k(const float* __restrict__ W2)
{
    __shared__ float t[32][33];
    const int n0 = blockIdx.x * 32;
    const int k0 = blockIdx.y * 32;
    const int tid = threadIdx.x;
#pragma unroll
    for (int i = 0; i < 4; i++) {
        int idx = tid + i * 256;
        int kr = idx >> 5;
        int nc = idx & 31;
        t[kr][nc] = W2[(size_t)(k0 + kr) * 8192 + n0 + nc];
    }
    __syncthreads();
    int n = tid >> 3;
    int kc = tid & 7;
    BFQ hi, lo;
#pragma unroll
    for (int j = 0; j < 4; j++) {
        float v = t[kc*4 + j][n];
        hi.h[j] = __float2bfloat16(v);
        lo.h[j] = __float2bfloat16(v - __bfloat162float(hi.h[j]));
    }
    size_t o = (size_t)(n0 + n) * 1024 + k0 + kc*4;
    *(uint2*)(&g_w2h[o]) = hi.u;
    *(uint2*)(&g_w2l[o]) = lo.u;
}

// ---------------------------------------------------------------------------
// GEMM2 via HMMA bf16 split-2: attention[256,8192] = h @ W2 + b2
// BM=128 BN=64 BK=32, 256 threads (8 warps: 4m x 2n), warp tile 32x32.
// smem buffer layout (bytes): A_H 0..10240, A_L ..20480, B_H ..25600, B_L ..30720
// ---------------------------------------------------------------------------
__global__ void __launch_bounds__(256) hgemm2_k(
        const float* __restrict__ bias, float* __restrict__ C)
{
    extern __shared__ __align__(16) char hsm[];
    const unsigned sbase = (unsigned)__cvta_generic_to_shared(hsm);
    const int tid = threadIdx.x;
    const int lane = tid & 31;
    const int wid = tid >> 5;
    const int wm = wid & 3;
    const int wn = wid >> 2;
    const int n0 = blockIdx.x * 64;
    const int m0 = blockIdx.y * 128;

    const int ar0 = tid >> 2;
    const int akq = tid & 3;
    const int ar1 = ar0 + 64;
    const unsigned dA0 = (unsigned)(ar0*40 + akq*8) * 2u;
    const unsigned dA1 = (unsigned)(ar1*40 + akq*8) * 2u;
    const unsigned dB  = (unsigned)(ar0*40 + akq*8) * 2u;

    unsigned aOffH[2];
#pragma unroll
    for (int ti = 0; ti < 2; ti++) {
        int row = wm*32 + ti*16 + (lane & 15);
        int kb  = (lane >> 4) * 8;
        aOffH[ti] = (unsigned)(row*40 + kb) * 2u;
    }
    unsigned bOffH[4];
#pragma unroll
    for (int tj = 0; tj < 4; tj++) {
        int row = wn*32 + tj*8 + (lane & 7);
        int kb  = ((lane >> 3) & 1) * 8;
        bOffH[tj] = 20480u + (unsigned)(row*40 + kb) * 2u;
    }

    float acc[2][4][4];
#pragma unroll
    for (int ti = 0; ti < 2; ti++)
#pragma unroll
        for (int tj = 0; tj < 4; tj++) {
            acc[ti][tj][0] = 0.f; acc[ti][tj][1] = 0.f;
            acc[ti][tj][2] = 0.f; acc[ti][tj][3] = 0.f;
        }

    const size_t sa0 = (size_t)(m0 + ar0) * 1024 + akq*8;
    const size_t sa1 = (size_t)(m0 + ar1) * 1024 + akq*8;
    const size_t sb  = (size_t)(n0 + ar0) * 1024 + akq*8;

    uint4 rah0 = *(const uint4*)(&g_hh[sa0]);
    uint4 rah1 = *(const uint4*)(&g_hh[sa1]);
    uint4 ral0 = *(const uint4*)(&g_hl[sa0]);
    uint4 ral1 = *(const uint4*)(&g_hl[sa1]);
    uint4 rbh  = *(const uint4*)(&g_w2h[sb]);
    uint4 rbl  = *(const uint4*)(&g_w2l[sb]);
    {
        char* p = hsm;
        *(uint4*)(p + dA0) = rah0;
        *(uint4*)(p + dA1) = rah1;
        *(uint4*)(p + 10240 + dA0) = ral0;
        *(uint4*)(p + 10240 + dA1) = ral1;
        *(uint4*)(p + 20480 + dB) = rbh;
        *(uint4*)(p + 25600 + dB) = rbl;
    }
    __syncthreads();

    for (int it = 0; it < 32; ++it) {
        const int cur = it & 1;
        if (it < 31) {
            int kk = (it + 1) * 32;
            rah0 = *(const uint4*)(&g_hh[sa0 + kk]);
            rah1 = *(const uint4*)(&g_hh[sa1 + kk]);
            ral0 = *(const uint4*)(&g_hl[sa0 + kk]);
            ral1 = *(const uint4*)(&g_hl[sa1 + kk]);
            rbh  = *(const uint4*)(&g_w2h[sb + kk]);
            rbl  = *(const uint4*)(&g_w2l[sb + kk]);
        }

        const unsigned base = sbase + (unsigned)cur * 30720u;
#pragma unroll
        for (int ks = 0; ks < 2; ks++) {
            const unsigned ko = (unsigned)ks * 32u;
            unsigned fah[2][4], fal[2][4], fbh[4][2], fbl[4][2];
#pragma unroll
            for (int ti = 0; ti < 2; ti++) {
                ldsm4(fah[ti], base + aOffH[ti] + ko);
                ldsm4(fal[ti], base + aOffH[ti] + 10240u + ko);
            }
#pragma unroll
            for (int tj = 0; tj < 4; tj++) {
                ldsm2(fbh[tj], base + bOffH[tj] + ko);
                ldsm2(fbl[tj], base + bOffH[tj] + 5120u + ko);
            }
#pragma unroll
            for (int ti = 0; ti < 2; ti++)
#pragma unroll
                for (int tj = 0; tj < 4; tj++) {
                    mma16816(acc[ti][tj], fah[ti], fbh[tj]);
                    mma16816(acc[ti][tj], fah[ti], fbl[tj]);
                    mma16816(acc[ti][tj], fal[ti], fbh[tj]);
                }
        }

        if (it < 31) {
            __syncthreads();
            char* p = hsm + (cur ^ 1) * 30720;
            *(uint4*)(p + dA0) = rah0;
            *(uint4*)(p + dA1) = rah1;
            *(uint4*)(p + 10240 + dA0) = ral0;
            *(uint4*)(p + 10240 + dA1) = ral1;
            *(uint4*)(p + 20480 + dB) = rbh;
            *(uint4*)(p + 25600 + dB) = rbl;
            __syncthreads();
        }
    }

    const int gq = lane >> 2;
    const int t2 = (lane & 3) * 2;
#pragma unroll
    for (int ti = 0; ti < 2; ti++) {
        int row = m0 + wm*32 + ti*16 + gq;
#pragma unroll
        for (int tj = 0; tj < 4; tj++) {
            int col = n0 + wn*32 + tj*8 + t2;
            float2 bb = *(const float2*)(bias + col);
            *(float2*)(C + (size_t)row * 8192 + col) =
                make_float2(acc[ti][tj][0] + bb.x, acc[ti][tj][1] + bb.y);
            *(float2*)(C + (size_t)(row + 8) * 8192 + col) =
                make_float2(acc[ti][tj][2] + bb.x, acc[ti][tj][3] + bb.y);
        }
    }
}

// ---------------------------------------------------------------------------
// Fused (round-5 winner, unchanged): block = (16 b, 8 u), 256 threads.
// ---------------------------------------------------------------------------
#define SM_FLOATS (NB*NU*SP + NU*16*16 + NU*64*16)

__global__ void __launch_bounds__(256) fused_attn(
        const float* __restrict__ attn,
        const float* __restrict__ Ma,
        const float* __restrict__ Mv,
        const float* __restrict__ temp,
        float* __restrict__ wout,
        float* __restrict__ outp)
{
    extern __shared__ float sm[];
    float*  sS   = sm;
    float*  sA   = sS + NB*NU*SP;
    float4* sMv4 = (float4*)(sA + NU*16*16);

    const int b0  = blockIdx.x * NB;
    const int u0  = blockIdx.y * NU;
    const int tid = threadIdx.x;
    const int lane = tid & 31;
    const int wu   = tid >> 5;
    const int u    = u0 + wu;

#pragma unroll
    for (int t = 0; t < 2; t++) {
        int idx = tid + t*256;
        int bi = idx >> 5;
        int uu = (idx >> 2) & 7;
        int dq = idx & 3;
        float4 v = *(const float4*)(attn + ((size_t)(b0+bi)*U_ + u0+uu)*D_ + dq*4);
        sA[(uu*16 + dq*4+0)*16 + bi] = v.x;
        sA[(uu*16 + dq*4+1)*16 + bi] = v.y;
        sA[(uu*16 + dq*4+2)*16 + bi] = v.z;
        sA[(uu*16 + dq*4+3)*16 + bi] = v.w;
    }
    const float tu = temp[u];
    __syncthreads();

    {
        const int tx = lane;
        float4 maq[2][2][4];
#pragma unroll
        for (int cc = 0; cc < 2; cc++) {
            int m = tx + 32*cc;
            const float4* p = (const float4*)(Ma + ((size_t)m*U_ + u)*D_);
#pragma unroll
            for (int dq = 0; dq < 4; dq++) maq[0][cc][dq] = p[dq];
        }
#pragma unroll
        for (int c4 = 0; c4 < 4; c4++) {
            const int buf = c4 & 1;
            if (c4 < 3) {
#pragma unroll
                for (int cc = 0; cc < 2; cc++) {
                    int m = (c4+1)*64 + tx + 32*cc;
                    const float4* p = (const float4*)(Ma + ((size_t)m*U_ + u)*D_);
#pragma unroll
                    for (int dq = 0; dq < 4; dq++) maq[buf ^ 1][cc][dq] = p[dq];
                }
            }
            ull acc[8][2];
#pragma unroll
            for (int bp = 0; bp < 8; bp++) { acc[bp][0] = 0ull; acc[bp][1] = 0ull; }

#pragma unroll
            for (int d = 0; d < 16; d++) {
                ull ap[8];
#pragma unroll
                for (int q = 0; q < 4; q++) {
                    F4U t; t.f = *(const float4*)(&sA[(wu*16 + d)*16 + q*4]);
                    ap[2*q] = t.p[0]; ap[2*q+1] = t.p[1];
                }
                F4U mq0; mq0.f = maq[buf][0][d>>2];
                F4U mq1; mq1.f = maq[buf][1][d>>2];
                ull md0 = pk2(mq0.s[d & 3], mq0.s[d & 3]);
                ull md1 = pk2(mq1.s[d & 3], mq1.s[d & 3]);
#pragma unroll
                for (int bp = 0; bp < 8; bp++) {
                    ffma2(acc[bp][0], ap[bp], md0);
                    ffma2(acc[bp][1], ap[bp], md1);
                }
            }
#pragma unroll
            for (int cc = 0; cc < 2; cc++) {
                int m = c4*64 + tx + 32*cc;
#pragma unroll
                for (int bp = 0; bp < 8; bp++) {
                    float s0, s1;
                    upk2(acc[bp][cc], s0, s1);
                    int bA = 2*bp, bB = 2*bp + 1;
                    sS[(bA*NU + wu)*SP + m] = (m == b0 + bA) ? -INFINITY : s0 * tu;
                    sS[(bB*NU + wu)*SP + m] = (m == b0 + bB) ? -INFINITY : s1 * tu;
                }
            }
        }
    }
    __syncthreads();

    {
        int g  = tid & 7;
        int uu = (tid >> 3) & 7;
        int bq = tid >> 6;
#pragma unroll
        for (int i = 0; i < 4; i++) {
            int b = bq*4 + i;
            float* row = sS + (b*NU + uu)*SP + g;
            float v[32];
            float mx = -INFINITY;
#pragma unroll
            for (int j = 0; j < 32; j++) { v[j] = row[j*8]; mx = fmaxf(mx, v[j]); }
            float s = 0.f;
#pragma unroll
            for (int j = 0; j < 32; j++) { v[j] = __expf(v[j] - mx); s += v[j]; }
            float inv = 1.f / (8.f * s);
#pragma unroll
            for (int j = 0; j < 32; j++) row[j*8] = v[j] * inv;
        }
    }
    __syncthreads();

    {
        int b  = tid >> 4;
        int tl = tid & 15;
#pragma unroll
        for (int mi = 0; mi < 16; mi++) {
            int m = tl + 16*mi;
            float w8[8];
#pragma unroll
            for (int uu = 0; uu < 8; uu++) w8[uu] = sS[(b*NU + uu)*SP + m];
            float4* dst = (float4*)(wout + ((size_t)(b0 + b)*M_ + m)*U_ + u0);
            dst[0] = make_float4(w8[0], w8[1], w8[2], w8[3]);
            dst[1] = make_float4(w8[4], w8[5], w8[6], w8[7]);
        }
    }

    {
        const int mseg = lane & 7;
        const int dg   = (lane >> 3) & 1;
        const int bg   = lane >> 4;

        ull acc[8][4];
#pragma unroll
        for (int bi = 0; bi < 8; bi++)
#pragma unroll
            for (int dp = 0; dp < 4; dp++) acc[bi][dp] = 0ull;

#pragma unroll
        for (int c4 = 0; c4 < 4; c4++) {
            __syncthreads();
#pragma unroll
            for (int t = 0; t < 8; t++) {
                int idx = tid + t*256;
                int mloc = idx >> 5;
                int uu = (idx >> 2) & 7;
                int dq = idx & 3;
                float4 v = *(const float4*)(Mv + ((size_t)(c4*64 + mloc)*U_ + u0+uu)*D_ + dq*4);
                sMv4[uu*256 + mloc*4 + (dq ^ ((mloc >> 3) & 3))] = v;
            }
            __syncthreads();

#pragma unroll
            for (int h = 0; h < 2; h++) {
                int mbase = c4*64 + mseg*8 + h*4;
                F4U w4[8];
#pragma unroll
                for (int bi = 0; bi < 8; bi++)
                    w4[bi].f = *(const float4*)(&sS[((bg*8 + bi)*NU + wu)*SP + mbase]);
                ull mvp[4][4];
#pragma unroll
                for (int mi = 0; mi < 4; mi++) {
#pragma unroll
                    for (int k = 0; k < 2; k++) {
                        int mloc = mseg*8 + h*4 + mi;
                        F4U v; v.f = sMv4[wu*256 + mloc*4 + ((dg*2 + k) ^ (mseg & 3))];
                        mvp[mi][k*2]   = v.p[0];
                        mvp[mi][k*2+1] = v.p[1];
                    }
                }
#pragma unroll
                for (int mi = 0; mi < 4; mi++)
#pragma unroll
                    for (int bi = 0; bi < 8; bi++) {
                        ull wd = pk2(w4[bi].s[mi], w4[bi].s[mi]);
                        ffma2(acc[bi][0], wd, mvp[mi][0]);
                        ffma2(acc[bi][1], wd, mvp[mi][1]);
                        ffma2(acc[bi][2], wd, mvp[mi][2]);
                        ffma2(acc[bi][3], wd, mvp[mi][3]);
                    }
            }
        }

#pragma unroll
        for (int off = 1; off < 8; off <<= 1) {
#pragma unroll
            for (int bi = 0; bi < 8; bi++)
#pragma unroll
                for (int dp = 0; dp < 4; dp++) {
                    ull o = __shfl_xor_sync(0xffffffffu, acc[bi][dp], off);
                    acc[bi][dp] = add2(acc[bi][dp], o);
                }
        }
        if (mseg == 0) {
#pragma unroll
            for (int bi = 0; bi < 8; bi++) {
                float o[8];
                upk2(acc[bi][0], o[0], o[1]);
                upk2(acc[bi][1], o[2], o[3]);
                upk2(acc[bi][2], o[4], o[5]);
                upk2(acc[bi][3], o[6], o[7]);
                float* dst = outp + ((size_t)(b0 + bg*8 + bi)*U_ + u)*D_ + dg*8;
                *(float4*)(dst)     = make_float4(o[0], o[1], o[2], o[3]);
                *(float4*)(dst + 4) = make_float4(o[4], o[5], o[6], o[7]);
            }
        }
    }
}

// ---------------------------------------------------------------------------
extern "C" void kernel_launch(void* const* d_in, const int* in_sizes, int n_in,
                              void* d_out, int out_size)
{
    const float* x    = (const float*)d_in[0];
    const float* W1   = (const float*)d_in[1];
    const float* b1   = (const float*)d_in[2];
    const float* W2   = (const float*)d_in[3];
    const float* b2   = (const float*)d_in[4];
    const float* temp = (const float*)d_in[5];
    const float* Ma   = (const float*)d_in[6];
    const float* Mv   = (const float*)d_in[7];

    float* attn = (float*)d_out;
    float* wout = attn + (size_t)B_ * U_ * D_;
    float* outp = wout + (size_t)B_ * B_ * U_;

    int smem3 = SM_FLOATS * (int)sizeof(float);
    cudaFuncSetAttribute(hgemm2_k, cudaFuncAttributeMaxDynamicSharedMemorySize, 61440);
    cudaFuncSetAttribute(fused_attn, cudaFuncAttributeMaxDynamicSharedMemorySize, smem3);

    dim3 gW2(256, 32, 1);
    dim3 gG1(32, 4, 4);
    dim3 gG2(128, 2, 1);
    dim3 gF(16, 64, 1);

    w2conv_k<<<gW2, 256>>>(W2);
    gemm1_partial<<<gG1, 128>>>(x, W1);
    reduce_bias_h<<<256, 256>>>(b1);
    hgemm2_k<<<gG2, 256, 61440>>>(b2, attn);
    fused_attn<<<gF, 256, smem3>>>(attn, Ma, Mv, temp, wout, outp);
}

// round 10
// speedup vs baseline: 1.4128x; 1.0741x over previous
#include <cuda_runtime.h>
#include <cuda_bf16.h>
#include <cmath>

#define B_   256
#define U_   512
#define D_   16
#define M_   256

// device globals (allocation-free rule)
__device__ float g_hp[4][B_ * 1024];                 // GEMM1 split-K partials
__device__ __nv_bfloat16 g_hh[B_ * 1024];            // h hi [m][k]
__device__ __nv_bfloat16 g_hl[B_ * 1024];            // h lo
__device__ __nv_bfloat16 g_w2h[8192 * 1024];         // W2^T hi [n][k]
__device__ __nv_bfloat16 g_w2l[8192 * 1024];         // W2^T lo
__device__ __nv_bfloat16 g_ah[B_ * 8192];            // attention hi [b][u*16+d]
__device__ __nv_bfloat16 g_al[B_ * 8192];            // attention lo
__device__ __nv_bfloat16 g_mah[U_ * M_ * D_];        // Ma hi [u][m][d]
__device__ __nv_bfloat16 g_mal[U_ * M_ * D_];
__device__ __nv_bfloat16 g_mvth[U_ * D_ * M_];       // Mv^T hi [u][d][m]
__device__ __nv_bfloat16 g_mvtl[U_ * D_ * M_];

typedef unsigned long long ull;
union F4U { float4 f; ull p[2]; float s[4]; };

__device__ __forceinline__ ull pk2(float a, float b) {
    ull r; asm("mov.b64 %0, {%1, %2};" : "=l"(r) : "f"(a), "f"(b)); return r;
}
__device__ __forceinline__ void upk2(ull v, float& a, float& b) {
    asm("mov.b64 {%0, %1}, %2;" : "=f"(a), "=f"(b) : "l"(v));
}
__device__ __forceinline__ void ffma2(ull& d, ull a, ull b) {
    asm("fma.rn.f32x2 %0, %1, %2, %0;" : "+l"(d) : "l"(a), "l"(b));
}
__device__ __forceinline__ void ldsm4(unsigned* r, unsigned addr) {
    asm volatile("ldmatrix.sync.aligned.m8n8.x4.shared.b16 {%0,%1,%2,%3}, [%4];"
        : "=r"(r[0]), "=r"(r[1]), "=r"(r[2]), "=r"(r[3]) : "r"(addr));
}
__device__ __forceinline__ void ldsm2(unsigned* r, unsigned addr) {
    asm volatile("ldmatrix.sync.aligned.m8n8.x2.shared.b16 {%0,%1}, [%2];"
        : "=r"(r[0]), "=r"(r[1]) : "r"(addr));
}
__device__ __forceinline__ void mma16816(float* d, const unsigned* a, const unsigned* b) {
    asm volatile(
        "mma.sync.aligned.m16n8k16.row.col.f32.bf16.bf16.f32 "
        "{%0,%1,%2,%3}, {%4,%5,%6,%7}, {%8,%9}, {%0,%1,%2,%3};"
        : "+f"(d[0]), "+f"(d[1]), "+f"(d[2]), "+f"(d[3])
        : "r"(a[0]), "r"(a[1]), "r"(a[2]), "r"(a[3]), "r"(b[0]), "r"(b[1]));
}
__device__ __forceinline__ unsigned pkbf2(float a, float b) {
    __nv_bfloat162 t = __floats2bfloat162_rn(a, b);
    return *(unsigned*)&t;
}

// ---------------------------------------------------------------------------
// GEMM1 partials (fp32 f32x2): g_hp[z] = x @ W1 k-slice
// ---------------------------------------------------------------------------
__global__ void __launch_bounds__(128) gemm1_partial(
        const float* __restrict__ A, const float* __restrict__ Bm)
{
    __shared__ float As[16][68];
    __shared__ float Bs[16][32];

    const int tid = threadIdx.x;
    const int bx = blockIdx.x, by = blockIdx.y, bz = blockIdx.z;
    const int kBegin = bz * 256;
    const int tx = tid & 7;
    const int ty = tid >> 3;

    ull acc2[2][4];
    acc2[0][0]=0ull; acc2[0][1]=0ull; acc2[0][2]=0ull; acc2[0][3]=0ull;
    acc2[1][0]=0ull; acc2[1][1]=0ull; acc2[1][2]=0ull; acc2[1][3]=0ull;

    const float* Ablk = A + (size_t)by * 64 * 1024;
    const float* Bblk = Bm + bx * 32;

    const int ar = tid >> 2;
    const int akq = tid & 3;
    const int bkr = tid >> 3;
    const int bnq = tid & 7;

    {
        float4 v0 = *(const float4*)(Ablk + (size_t)ar * 1024 + kBegin + akq * 4);
        As[akq*4+0][ar] = v0.x; As[akq*4+1][ar] = v0.y;
        As[akq*4+2][ar] = v0.z; As[akq*4+3][ar] = v0.w;
        float4 v1 = *(const float4*)(Ablk + (size_t)(ar+32) * 1024 + kBegin + akq * 4);
        As[akq*4+0][ar+32] = v1.x; As[akq*4+1][ar+32] = v1.y;
        As[akq*4+2][ar+32] = v1.z; As[akq*4+3][ar+32] = v1.w;
        float4 vb = *(const float4*)(Bblk + (size_t)(kBegin + bkr) * 1024 + bnq * 4);
        *(float4*)(&Bs[bkr][bnq*4]) = vb;
    }
    __syncthreads();

    for (int k0 = kBegin; k0 < kBegin + 256; k0 += 16) {
        const bool more = (k0 + 16) < (kBegin + 256);
        float4 nA0, nA1, nB0;
        if (more) {
            nA0 = *(const float4*)(Ablk + (size_t)ar * 1024 + k0 + 16 + akq * 4);
            nA1 = *(const float4*)(Ablk + (size_t)(ar+32) * 1024 + k0 + 16 + akq * 4);
            nB0 = *(const float4*)(Bblk + (size_t)(k0 + 16 + bkr) * 1024 + bnq * 4);
        }
#pragma unroll
        for (int k = 0; k < 16; k++) {
            F4U ta; ta.f = *(const float4*)(&As[k][ty*4]);
            float4 vb = *(const float4*)(&Bs[k][tx*4]);
            ull bd0 = pk2(vb.x, vb.x);
            ull bd1 = pk2(vb.y, vb.y);
            ull bd2 = pk2(vb.z, vb.z);
            ull bd3 = pk2(vb.w, vb.w);
            ffma2(acc2[0][0], ta.p[0], bd0);
            ffma2(acc2[0][1], ta.p[0], bd1);
            ffma2(acc2[0][2], ta.p[0], bd2);
            ffma2(acc2[0][3], ta.p[0], bd3);
            ffma2(acc2[1][0], ta.p[1], bd0);
            ffma2(acc2[1][1], ta.p[1], bd1);
            ffma2(acc2[1][2], ta.p[1], bd2);
            ffma2(acc2[1][3], ta.p[1], bd3);
        }
        if (more) {
            __syncthreads();
            As[akq*4+0][ar] = nA0.x; As[akq*4+1][ar] = nA0.y;
            As[akq*4+2][ar] = nA0.z; As[akq*4+3][ar] = nA0.w;
            As[akq*4+0][ar+32] = nA1.x; As[akq*4+1][ar+32] = nA1.y;
            As[akq*4+2][ar+32] = nA1.z; As[akq*4+3][ar+32] = nA1.w;
            *(float4*)(&Bs[bkr][bnq*4]) = nB0;
            __syncthreads();
        }
    }

    float* Cs = &g_hp[bz][0];
#pragma unroll
    for (int r2 = 0; r2 < 2; r2++) {
        float s0[4], s1[4];
        upk2(acc2[r2][0], s0[0], s1[0]);
        upk2(acc2[r2][1], s0[1], s1[1]);
        upk2(acc2[r2][2], s0[2], s1[2]);
        upk2(acc2[r2][3], s0[3], s1[3]);
        int row0 = by*64 + ty*4 + 2*r2;
        int col = bx*32 + tx*4;
        *(float4*)(Cs + (size_t)row0 * 1024 + col) =
            make_float4(s0[0], s0[1], s0[2], s0[3]);
        *(float4*)(Cs + (size_t)(row0 + 1) * 1024 + col) =
            make_float4(s1[0], s1[1], s1[2], s1[3]);
    }
}

// ---------------------------------------------------------------------------
// reduce GEMM1 partials + bias -> bf16 hi/lo planes of h
// ---------------------------------------------------------------------------
__global__ void __launch_bounds__(256) reduce_bias_h(const float* __restrict__ bias)
{
    int i = blockIdx.x * 256 + threadIdx.x;
    int col4 = i & 255;
    float4 a = *(const float4*)(&g_hp[0][i*4]);
    float4 b = *(const float4*)(&g_hp[1][i*4]);
    float4 c = *(const float4*)(&g_hp[2][i*4]);
    float4 d = *(const float4*)(&g_hp[3][i*4]);
    float4 bb = *(const float4*)(bias + col4*4);
    float v0 = a.x + b.x + c.x + d.x + bb.x;
    float v1 = a.y + b.y + c.y + d.y + bb.y;
    float v2 = a.z + b.z + c.z + d.z + bb.z;
    float v3 = a.w + b.w + c.w + d.w + bb.w;

    unsigned h01 = pkbf2(v0, v1);
    unsigned h23 = pkbf2(v2, v3);
    __nv_bfloat162 hh01 = *(__nv_bfloat162*)&h01;
    __nv_bfloat162 hh23 = *(__nv_bfloat162*)&h23;
    unsigned l01 = pkbf2(v0 - __low2float(hh01), v1 - __high2float(hh01));
    unsigned l23 = pkbf2(v2 - __low2float(hh23), v3 - __high2float(hh23));
    *(uint2*)(&g_hh[i*4]) = make_uint2(h01, h23);
    *(uint2*)(&g_hl[i*4]) = make_uint2(l01, l23);
}

// ---------------------------------------------------------------------------
// W2 [k=1024][n=8192] fp32 -> transposed bf16 hi/lo planes [n][k]
// ---------------------------------------------------------------------------
__global__ void __launch_bounds__(256) w2conv_k(const float* __restrict__ W2)
{
    __shared__ float t[32][33];
    const int n0 = blockIdx.x * 32;
    const int k0 = blockIdx.y * 32;
    const int tid = threadIdx.x;
#pragma unroll
    for (int i = 0; i < 4; i++) {
        int idx = tid + i * 256;
        int kr = idx >> 5;
        int nc = idx & 31;
        t[kr][nc] = W2[(size_t)(k0 + kr) * 8192 + n0 + nc];
    }
    __syncthreads();
    int n = tid >> 3;
    int kc = tid & 7;
    float v0 = t[kc*4+0][n], v1 = t[kc*4+1][n], v2 = t[kc*4+2][n], v3 = t[kc*4+3][n];
    unsigned h01 = pkbf2(v0, v1);
    unsigned h23 = pkbf2(v2, v3);
    __nv_bfloat162 hh01 = *(__nv_bfloat162*)&h01;
    __nv_bfloat162 hh23 = *(__nv_bfloat162*)&h23;
    unsigned l01 = pkbf2(v0 - __low2float(hh01), v1 - __high2float(hh01));
    unsigned l23 = pkbf2(v2 - __low2float(hh23), v3 - __high2float(hh23));
    size_t o = (size_t)(n0 + n) * 1024 + k0 + kc*4;
    *(uint2*)(&g_w2h[o]) = make_uint2(h01, h23);
    *(uint2*)(&g_w2l[o]) = make_uint2(l01, l23);
}

// ---------------------------------------------------------------------------
// Ma [m][u][d] -> g_mah/g_mal [u][m][d];  Mv -> g_mvth/g_mvtl [u][d][m]
// ---------------------------------------------------------------------------
__global__ void __launch_bounds__(256) mvconv_k(
        const float* __restrict__ Ma, const float* __restrict__ Mv)
{
    __shared__ float tv[16][68];
    const int u  = blockIdx.x;
    const int m0 = blockIdx.y * 64;
    const int t  = threadIdx.x;
    const int ml = t >> 2;
    const int q  = t & 3;

    // Ma: straight convert to [u][m][d]
    {
        float4 v = *(const float4*)(Ma + ((size_t)(m0+ml)*512 + u)*16 + q*4);
        unsigned h01 = pkbf2(v.x, v.y);
        unsigned h23 = pkbf2(v.z, v.w);
        __nv_bfloat162 hh01 = *(__nv_bfloat162*)&h01;
        __nv_bfloat162 hh23 = *(__nv_bfloat162*)&h23;
        unsigned l01 = pkbf2(v.x - __low2float(hh01), v.y - __high2float(hh01));
        unsigned l23 = pkbf2(v.z - __low2float(hh23), v.w - __high2float(hh23));
        size_t o = ((size_t)u*256 + m0 + ml)*16 + q*4;
        *(uint2*)(&g_mah[o]) = make_uint2(h01, h23);
        *(uint2*)(&g_mal[o]) = make_uint2(l01, l23);
    }
    // Mv: stage transpose
    {
        float4 v = *(const float4*)(Mv + ((size_t)(m0+ml)*512 + u)*16 + q*4);
        tv[q*4+0][ml] = v.x;
        tv[q*4+1][ml] = v.y;
        tv[q*4+2][ml] = v.z;
        tv[q*4+3][ml] = v.w;
    }
    __syncthreads();
    {
        int d = t >> 4;
        int mq = t & 15;
        float v0 = tv[d][mq*4+0], v1 = tv[d][mq*4+1];
        float v2 = tv[d][mq*4+2], v3 = tv[d][mq*4+3];
        unsigned h01 = pkbf2(v0, v1);
        unsigned h23 = pkbf2(v2, v3);
        __nv_bfloat162 hh01 = *(__nv_bfloat162*)&h01;
        __nv_bfloat162 hh23 = *(__nv_bfloat162*)&h23;
        unsigned l01 = pkbf2(v0 - __low2float(hh01), v1 - __high2float(hh01));
        unsigned l23 = pkbf2(v2 - __low2float(hh23), v3 - __high2float(hh23));
        size_t o = ((size_t)u*16 + d)*256 + m0 + mq*4;
        *(uint2*)(&g_mvth[o]) = make_uint2(h01, h23);
        *(uint2*)(&g_mvtl[o]) = make_uint2(l01, l23);
    }
}

// ---------------------------------------------------------------------------
// GEMM2 via HMMA bf16 split-2; epilogue also emits attention bf16 planes.
// ---------------------------------------------------------------------------
__global__ void __launch_bounds__(256) hgemm2_k(
        const float* __restrict__ bias, float* __restrict__ C)
{
    extern __shared__ __align__(16) char hsm[];
    const unsigned sbase = (unsigned)__cvta_generic_to_shared(hsm);
    const int tid = threadIdx.x;
    const int lane = tid & 31;
    const int wid = tid >> 5;
    const int wm = wid & 3;
    const int wn = wid >> 2;
    const int n0 = blockIdx.x * 64;
    const int m0 = blockIdx.y * 128;

    const int ar0 = tid >> 2;
    const int akq = tid & 3;
    const int ar1 = ar0 + 64;
    const unsigned dA0 = (unsigned)(ar0*40 + akq*8) * 2u;
    const unsigned dA1 = (unsigned)(ar1*40 + akq*8) * 2u;
    const unsigned dB  = (unsigned)(ar0*40 + akq*8) * 2u;

    unsigned aOffH[2];
#pragma unroll
    for (int ti = 0; ti < 2; ti++) {
        int row = wm*32 + ti*16 + (lane & 15);
        int kb  = (lane >> 4) * 8;
        aOffH[ti] = (unsigned)(row*40 + kb) * 2u;
    }
    unsigned bOffH[4];
#pragma unroll
    for (int tj = 0; tj < 4; tj++) {
        int row = wn*32 + tj*8 + (lane & 7);
        int kb  = ((lane >> 3) & 1) * 8;
        bOffH[tj] = 20480u + (unsigned)(row*40 + kb) * 2u;
    }

    float acc[2][4][4];
#pragma unroll
    for (int ti = 0; ti < 2; ti++)
#pragma unroll
        for (int tj = 0; tj < 4; tj++) {
            acc[ti][tj][0] = 0.f; acc[ti][tj][1] = 0.f;
            acc[ti][tj][2] = 0.f; acc[ti][tj][3] = 0.f;
        }

    const size_t sa0 = (size_t)(m0 + ar0) * 1024 + akq*8;
    const size_t sa1 = (size_t)(m0 + ar1) * 1024 + akq*8;
    const size_t sb  = (size_t)(n0 + ar0) * 1024 + akq*8;

    uint4 rah0 = *(const uint4*)(&g_hh[sa0]);
    uint4 rah1 = *(const uint4*)(&g_hh[sa1]);
    uint4 ral0 = *(const uint4*)(&g_hl[sa0]);
    uint4 ral1 = *(const uint4*)(&g_hl[sa1]);
    uint4 rbh  = *(const uint4*)(&g_w2h[sb]);
    uint4 rbl  = *(const uint4*)(&g_w2l[sb]);
    {
        char* p = hsm;
        *(uint4*)(p + dA0) = rah0;
        *(uint4*)(p + dA1) = rah1;
        *(uint4*)(p + 10240 + dA0) = ral0;
        *(uint4*)(p + 10240 + dA1) = ral1;
        *(uint4*)(p + 20480 + dB) = rbh;
        *(uint4*)(p + 25600 + dB) = rbl;
    }
    __syncthreads();

    for (int it = 0; it < 32; ++it) {
        const int cur = it & 1;
        if (it < 31) {
            int kk = (it + 1) * 32;
            rah0 = *(const uint4*)(&g_hh[sa0 + kk]);
            rah1 = *(const uint4*)(&g_hh[sa1 + kk]);
            ral0 = *(const uint4*)(&g_hl[sa0 + kk]);
            ral1 = *(const uint4*)(&g_hl[sa1 + kk]);
            rbh  = *(const uint4*)(&g_w2h[sb + kk]);
            rbl  = *(const uint4*)(&g_w2l[sb + kk]);
        }
        const unsigned base = sbase + (unsigned)cur * 30720u;
#pragma unroll
        for (int ks = 0; ks < 2; ks++) {
            const unsigned ko = (unsigned)ks * 32u;
            unsigned fah[2][4], fal[2][4], fbh[4][2], fbl[4][2];
#pragma unroll
            for (int ti = 0; ti < 2; ti++) {
                ldsm4(fah[ti], base + aOffH[ti] + ko);
                ldsm4(fal[ti], base + aOffH[ti] + 10240u + ko);
            }
#pragma unroll
            for (int tj = 0; tj < 4; tj++) {
                ldsm2(fbh[tj], base + bOffH[tj] + ko);
                ldsm2(fbl[tj], base + bOffH[tj] + 5120u + ko);
            }
#pragma unroll
            for (int ti = 0; ti < 2; ti++)
#pragma unroll
                for (int tj = 0; tj < 4; tj++) {
                    mma16816(acc[ti][tj], fah[ti], fbh[tj]);
                    mma16816(acc[ti][tj], fah[ti], fbl[tj]);
                    mma16816(acc[ti][tj], fal[ti], fbh[tj]);
                }
        }
        if (it < 31) {
            __syncthreads();
            char* p = hsm + (cur ^ 1) * 30720;
            *(uint4*)(p + dA0) = rah0;
            *(uint4*)(p + dA1) = rah1;
            *(uint4*)(p + 10240 + dA0) = ral0;
            *(uint4*)(p + 10240 + dA1) = ral1;
            *(uint4*)(p + 20480 + dB) = rbh;
            *(uint4*)(p + 25600 + dB) = rbl;
            __syncthreads();
        }
    }

    const int gq = lane >> 2;
    const int t2 = (lane & 3) * 2;
#pragma unroll
    for (int ti = 0; ti < 2; ti++) {
        int row = m0 + wm*32 + ti*16 + gq;
#pragma unroll
        for (int tj = 0; tj < 4; tj++) {
            int col = n0 + wn*32 + tj*8 + t2;
            float2 bb = *(const float2*)(bias + col);
            float v0 = acc[ti][tj][0] + bb.x;
            float v1 = acc[ti][tj][1] + bb.y;
            float v2 = acc[ti][tj][2] + bb.x;
            float v3 = acc[ti][tj][3] + bb.y;
            *(float2*)(C + (size_t)row * 8192 + col) = make_float2(v0, v1);
            *(float2*)(C + (size_t)(row + 8) * 8192 + col) = make_float2(v2, v3);
            unsigned h01 = pkbf2(v0, v1);
            __nv_bfloat162 hh01 = *(__nv_bfloat162*)&h01;
            unsigned l01 = pkbf2(v0 - __low2float(hh01), v1 - __high2float(hh01));
            *(unsigned*)(&g_ah[(size_t)row*8192 + col]) = h01;
            *(unsigned*)(&g_al[(size_t)row*8192 + col]) = l01;
            unsigned h23 = pkbf2(v2, v3);
            __nv_bfloat162 hh23 = *(__nv_bfloat162*)&h23;
            unsigned l23 = pkbf2(v2 - __low2float(hh23), v3 - __high2float(hh23));
            *(unsigned*)(&g_ah[(size_t)(row+8)*8192 + col]) = h23;
            *(unsigned*)(&g_al[(size_t)(row+8)*8192 + col]) = l23;
        }
    }
}

// ---------------------------------------------------------------------------
// Fused v5 (HMMA): block = (16 b, 8 u), warp <-> u, one __syncthreads.
// smem: sS fp32 [128 rows (u*16+b)][264]        0      .. 135168
//       sA bf16 [u][16 b][40 (hi16,lo16,pad)]   135168 .. 145408
//       sX per-u 5120B slice (Ma chunk / W staging)    .. 186368
//       sY per-u 4352B slice (MvT chunk)               .. 221184
// ---------------------------------------------------------------------------
__global__ void __launch_bounds__(256) fused_attn(
        const float* __restrict__ temp,
        float* __restrict__ wout,
        float* __restrict__ outp)
{
    extern __shared__ __align__(16) char smc[];
    float* sS = (float*)smc;
    const unsigned sbase = (unsigned)__cvta_generic_to_shared(smc);

    const int b0  = blockIdx.x * 16;
    const int u0  = blockIdx.y * 8;
    const int tid = threadIdx.x;
    const int lane = tid & 31;
    const int wu   = tid >> 5;
    const int ug   = u0 + wu;

    const unsigned sAu = sbase + 135168u + (unsigned)wu * 1280u;
    const unsigned sXu = sbase + 145408u + (unsigned)wu * 5120u;
    const unsigned sYu = sbase + 186368u + (unsigned)wu * 4352u;
    char* cAu = smc + 135168 + wu * 1280;
    char* cXu = smc + 145408 + wu * 5120;
    char* cYu = smc + 186368 + wu * 4352;

    const float tu = temp[ug];

    // ---- stage 0: attn bf16 -> sA (warp-private) ----
    {
        int b = lane >> 1, half = lane & 1;
        size_t gi = (size_t)(b0 + b) * 8192 + (size_t)ug * 16 + half * 8;
        uint4 vh = *(const uint4*)(&g_ah[gi]);
        uint4 vl = *(const uint4*)(&g_al[gi]);
        char* pa = cAu + b*80 + half*16;
        *(uint4*)pa = vh;
        *(uint4*)(pa + 32) = vl;
    }
    __syncwarp();

    unsigned fa_h[4], fa_l[4];
    {
        unsigned a = sAu + (unsigned)((lane & 15) * 80 + (lane >> 4) * 16);
        ldsm4(fa_h, a);
        ldsm4(fa_l, a + 32u);
    }

    // ---- stage 1: scores via HMMA, chunks of 64 m ----
    {
        uint4 pfh[4], pfl[4];
#pragma unroll
        for (int t = 0; t < 4; t++) {
            int idx = lane + t*32;
            int ml = idx >> 1, half = idx & 1;
            size_t gi = ((size_t)ug*256 + ml)*16 + half*8;
            pfh[t] = *(const uint4*)(&g_mah[gi]);
            pfl[t] = *(const uint4*)(&g_mal[gi]);
        }
        for (int c = 0; c < 4; c++) {
#pragma unroll
            for (int t = 0; t < 4; t++) {
                int idx = lane + t*32;
                int ml = idx >> 1, half = idx & 1;
                char* p = cXu + ml*80 + half*16;
                *(uint4*)p = pfh[t];
                *(uint4*)(p + 32) = pfl[t];
            }
            __syncwarp();
            if (c < 3) {
#pragma unroll
                for (int t = 0; t < 4; t++) {
                    int idx = lane + t*32;
                    int ml = idx >> 1, half = idx & 1;
                    size_t gi = ((size_t)ug*256 + (c+1)*64 + ml)*16 + half*8;
                    pfh[t] = *(const uint4*)(&g_mah[gi]);
                    pfl[t] = *(const uint4*)(&g_mal[gi]);
                }
            }
#pragma unroll
            for (int tj = 0; tj < 8; tj++) {
                unsigned fb_h[2], fb_l[2];
                unsigned ba = sXu + (unsigned)((tj*8 + (lane & 7))*80 + ((lane >> 3) & 1)*16);
                ldsm2(fb_h, ba);
                ldsm2(fb_l, ba + 32u);
                float d4[4];
                d4[0] = 0.f; d4[1] = 0.f; d4[2] = 0.f; d4[3] = 0.f;
                mma16816(d4, fa_h, fb_h);
                mma16816(d4, fa_h, fb_l);
                mma16816(d4, fa_l, fb_h);
                int gq = lane >> 2, t2 = (lane & 3) * 2;
                int m = c*64 + tj*8 + t2;
                float s0 = (m     == b0 + gq)     ? -INFINITY : d4[0] * tu;
                float s1 = (m + 1 == b0 + gq)     ? -INFINITY : d4[1] * tu;
                float s2 = (m     == b0 + gq + 8) ? -INFINITY : d4[2] * tu;
                float s3 = (m + 1 == b0 + gq + 8) ? -INFINITY : d4[3] * tu;
                *(float2*)(sS + (wu*16 + gq)*264 + m)     = make_float2(s0, s1);
                *(float2*)(sS + (wu*16 + gq + 8)*264 + m) = make_float2(s2, s3);
            }
            __syncwarp();
        }
    }

    // ---- stage 2: grouped softmax (warp-private in u) ----
    {
        int g  = lane & 7;
        int b2 = lane >> 3;
#pragma unroll
        for (int i = 0; i < 4; i++) {
            int b = b2 + 4*i;
            float* row = sS + (wu*16 + b)*264 + g;
            float v[32];
            float mx = -INFINITY;
#pragma unroll
            for (int j = 0; j < 32; j++) { v[j] = row[j*8]; mx = fmaxf(mx, v[j]); }
            float s = 0.f;
#pragma unroll
            for (int j = 0; j < 32; j++) { v[j] = __expf(v[j] - mx); s += v[j]; }
            float inv = 1.f / (8.f * s);
#pragma unroll
            for (int j = 0; j < 32; j++) row[j*8] = v[j] * inv;
        }
    }
    __syncthreads();   // the ONLY block sync: weights gather reads all u rows

    // ---- stage 2b: weights store [b][m][u0..u0+7] ----
    {
        int b  = tid >> 4;
        int tl = tid & 15;
#pragma unroll
        for (int mi = 0; mi < 16; mi++) {
            int m = tl + 16*mi;
            float w8[8];
#pragma unroll
            for (int uu = 0; uu < 8; uu++) w8[uu] = sS[(uu*16 + b)*264 + m];
            float4* dst = (float4*)(wout + ((size_t)(b0 + b)*256 + m)*512 + u0);
            dst[0] = make_float4(w8[0], w8[1], w8[2], w8[3]);
            dst[1] = make_float4(w8[4], w8[5], w8[6], w8[7]);
        }
    }

    // ---- stage 3: outputs via HMMA, chunks of 64 m ----
    {
        float acc3[2][4];
        acc3[0][0]=0.f; acc3[0][1]=0.f; acc3[0][2]=0.f; acc3[0][3]=0.f;
        acc3[1][0]=0.f; acc3[1][1]=0.f; acc3[1][2]=0.f; acc3[1][3]=0.f;

        uint4 pvh[4], pvl[4];
#pragma unroll
        for (int t = 0; t < 4; t++) {
            int idx = lane + t*32;
            int d = idx >> 3, seg = idx & 7;
            size_t gi = ((size_t)ug*16 + d)*256 + seg*8;
            pvh[t] = *(const uint4*)(&g_mvth[gi]);
            pvl[t] = *(const uint4*)(&g_mvtl[gi]);
        }
        for (int c = 0; c < 4; c++) {
            // store MvT chunk
#pragma unroll
            for (int t = 0; t < 4; t++) {
                int idx = lane + t*32;
                int d = idx >> 3, seg = idx & 7;
                char* p = cYu + d*272 + seg*16;
                *(uint4*)p = pvh[t];
                *(uint4*)(p + 128) = pvl[t];
            }
            // convert own-u W chunk fp32 -> bf16 hi/lo staging
            {
                int b = lane >> 1, half = lane & 1;
                const float* srow = sS + (wu*16 + b)*264 + c*64 + half*32;
                char* xrow = cXu + b*272 + half*64;
#pragma unroll
                for (int q = 0; q < 8; q++) {
                    float4 v = *(const float4*)(srow + q*4);
                    unsigned h01 = pkbf2(v.x, v.y);
                    unsigned h23 = pkbf2(v.z, v.w);
                    __nv_bfloat162 hh01 = *(__nv_bfloat162*)&h01;
                    __nv_bfloat162 hh23 = *(__nv_bfloat162*)&h23;
                    unsigned l01 = pkbf2(v.x - __low2float(hh01), v.y - __high2float(hh01));
                    unsigned l23 = pkbf2(v.z - __low2float(hh23), v.w - __high2float(hh23));
                    *(uint2*)(xrow + q*8) = make_uint2(h01, h23);
                    *(uint2*)(xrow + 128 + q*8) = make_uint2(l01, l23);
                }
            }
            __syncwarp();
            if (c < 3) {
#pragma unroll
                for (int t = 0; t < 4; t++) {
                    int idx = lane + t*32;
                    int d = idx >> 3, seg = idx & 7;
                    size_t gi = ((size_t)ug*16 + d)*256 + (c+1)*64 + seg*8;
                    pvh[t] = *(const uint4*)(&g_mvth[gi]);
                    pvl[t] = *(const uint4*)(&g_mvtl[gi]);
                }
            }
#pragma unroll
            for (int ks = 0; ks < 4; ks++) {
                unsigned fw_h[4], fw_l[4];
                unsigned aa = sXu + (unsigned)((lane & 15)*272 + ks*32 + (lane >> 4)*16);
                ldsm4(fw_h, aa);
                ldsm4(fw_l, aa + 128u);
#pragma unroll
                for (int tj = 0; tj < 2; tj++) {
                    unsigned fb_h[2], fb_l[2];
                    unsigned ba = sYu + (unsigned)((tj*8 + (lane & 7))*272 + ks*32 + ((lane >> 3) & 1)*16);
                    ldsm2(fb_h, ba);
                    ldsm2(fb_l, ba + 128u);
                    mma16816(acc3[tj], fw_h, fb_h);
                    mma16816(acc3[tj], fw_h, fb_l);
                    mma16816(acc3[tj], fw_l, fb_h);
                }
            }
            __syncwarp();
        }

        int gq = lane >> 2, t2 = (lane & 3) * 2;
        float* o0 = outp + ((size_t)(b0 + gq) * 512 + ug) * 16;
        float* o1 = outp + ((size_t)(b0 + gq + 8) * 512 + ug) * 16;
        *(float2*)(o0 + t2)     = make_float2(acc3[0][0], acc3[0][1]);
        *(float2*)(o0 + 8 + t2) = make_float2(acc3[1][0], acc3[1][1]);
        *(float2*)(o1 + t2)     = make_float2(acc3[0][2], acc3[0][3]);
        *(float2*)(o1 + 8 + t2) = make_float2(acc3[1][2], acc3[1][3]);
    }
}

// ---------------------------------------------------------------------------
extern "C" void kernel_launch(void* const* d_in, const int* in_sizes, int n_in,
                              void* d_out, int out_size)
{
    const float* x    = (const float*)d_in[0];
    const float* W1   = (const float*)d_in[1];
    const float* b1   = (const float*)d_in[2];
    const float* W2   = (const float*)d_in[3];
    const float* b2   = (const float*)d_in[4];
    const float* temp = (const float*)d_in[5];
    const float* Ma   = (const float*)d_in[6];
    const float* Mv   = (const float*)d_in[7];

    float* attn = (float*)d_out;
    float* wout = attn + (size_t)B_ * U_ * D_;
    float* outp = wout + (size_t)B_ * B_ * U_;

    cudaFuncSetAttribute(hgemm2_k, cudaFuncAttributeMaxDynamicSharedMemorySize, 61440);
    cudaFuncSetAttribute(fused_attn, cudaFuncAttributeMaxDynamicSharedMemorySize, 221184);

    dim3 gW2(256, 32, 1);
    dim3 gMV(512, 4, 1);
    dim3 gG1(32, 4, 4);
    dim3 gG2(128, 2, 1);
    dim3 gF(16, 64, 1);

    w2conv_k<<<gW2, 256>>>(W2);
    mvconv_k<<<gMV, 256>>>(Ma, Mv);
    gemm1_partial<<<gG1, 128>>>(x, W1);
    reduce_bias_h<<<256, 256>>>(b1);
    hgemm2_k<<<gG2, 256, 61440>>>(b2, attn);
    fused_attn<<<gF, 256, 221184>>>(temp, wout, outp);
}